// round 17
// baseline (speedup 1.0000x reference)
#include <cuda_runtime.h>
#include <cuda_bf16.h>
#include <cstdint>
#include <math.h>

#define Bq 128
#define Tq 512
#define Cq 100
#define Eq 64
#define Hq 256
#define KIN 320   // E+H

typedef unsigned long long ull;

// ---- scratch (device globals; no allocation in kernel_launch) ----
static __device__ unsigned g_r[(size_t)Bq * Tq * Eq];        // packed split-bf16 r
static __device__ __align__(16) unsigned g_h[2][Bq][Hq];     // packed split-bf16 h
static __device__ unsigned g_flag[8 * 16 * 8];               // [group][rank], 32B stride
static __device__ int g_sink;

// SMEM float offsets
#define ALO_F 0        // 17920: A_lo fragments [w][kk][lane] float4(4xb32)
#define BH_F  17920    //  2624: B_hi b32 [n][164]
#define BL_F  20544    //  2624: B_lo
#define RED_F 23168    //  2016: red [(g*16+j)*18 + b]
#define BS_F  25184    //   112: bias
#define SMEM_FLT 25344

__device__ __forceinline__ float sigmf_(float x) { return 1.f / (1.f + expf(-x)); }
__device__ __forceinline__ float softplusf_(float x) {
    return fmaxf(x, 0.f) + log1pf(expf(-fabsf(x)));
}
__device__ __forceinline__ float sigf(float x) {
    return __fdividef(1.f, 1.f + __expf(-x));
}
__device__ __forceinline__ float tanf_(float x) {
    return 1.f - 2.f * __fdividef(1.f, 1.f + __expf(2.f * x));
}
__device__ __forceinline__ float splusf(float x) {
    return fmaxf(x, 0.f) + __logf(1.f + __expf(-fabsf(x)));
}
__device__ __forceinline__ void bf16split_(float x, unsigned& h, unsigned& l) {
    __nv_bfloat16 bh = __float2bfloat16_rn(x);
    h = (unsigned)__bfloat16_as_ushort(bh);
    l = (unsigned)__bfloat16_as_ushort(__float2bfloat16_rn(x - __bfloat162float(bh)));
}
__device__ __forceinline__ unsigned packsplit_(float x) {
    unsigned h, l;
    bf16split_(x, h, l);
    return h | (l << 16);
}
__device__ __forceinline__ unsigned prmt_(unsigned a, unsigned b, unsigned c) {
    unsigned d;
    asm("prmt.b32 %0, %1, %2, %3;" : "=r"(d) : "r"(a), "r"(b), "r"(c));
    return d;
}

#define MMA_(d, a, b0, b1)                                                  \
    asm volatile("mma.sync.aligned.m16n8k16.row.col.f32.bf16.bf16.f32 "     \
                 "{%0,%1,%2,%3}, {%4,%5,%6,%7}, {%8,%9}, {%0,%1,%2,%3};"    \
                 : "+f"((d)[0]), "+f"((d)[1]), "+f"((d)[2]), "+f"((d)[3])   \
                 : "r"((a)[0]), "r"((a)[1]), "r"((a)[2]), "r"((a)[3]),      \
                   "r"(b0), "r"(b1))

__global__ void k_dummy() { if (threadIdx.x == 1024) g_sink = 1; }

// ---------------------------------------------------------------------------
// K1: rec_input -> packed split-bf16
// ---------------------------------------------------------------------------
__global__ __launch_bounds__(128) void k_embed(const float* __restrict__ marks,
                                               const float* __restrict__ Wemb) {
    int bt = blockIdx.x;
    __shared__ float sm[Cq];
    int tid = threadIdx.x;
    if (tid < Cq) sm[tid] = marks[(size_t)bt * Cq + tid];
    __syncthreads();
    if (tid < Eq) {
        float cnt = 0.f, s = 0.f;
        #pragma unroll
        for (int c = 0; c < Cq; c++) {
            float m = sm[c];
            cnt += m;
            s = fmaf(m, Wemb[c * Eq + tid], s);
        }
        g_r[(size_t)bt * Eq + tid] = packsplit_(s / fmaxf(cnt, 1.f));
    }
}

// ---------------------------------------------------------------------------
// K3: initial state -> out[b,0,:], packed g_h[0], reset flags
// ---------------------------------------------------------------------------
__global__ __launch_bounds__(256) void k_init(const float* __restrict__ init,
                                              float* __restrict__ out) {
    int b = blockIdx.x, k = threadIdx.x;
    if (b < 4) g_flag[b * 256 + k] = 0;
    float s0 = init[k], s1 = init[Hq + k], s2 = init[2 * Hq + k];
    float s3 = init[3 * Hq + k], s4 = init[4 * Hq + k], s5 = init[5 * Hq + k];
    float hd0 = tanhf(s0), cd0 = tanhf(s1), cb0 = tanhf(s2), c0 = tanhf(s3);
    float d0 = softplusf_(s4), o0 = sigmf_(s5);
    size_t base = (size_t)b * (Tq + 1) * (6 * Hq);
    out[base + 0 * Hq + k] = hd0;
    out[base + 1 * Hq + k] = o0;
    out[base + 2 * Hq + k] = cb0;
    out[base + 3 * Hq + k] = c0;
    out[base + 4 * Hq + k] = d0;
    out[base + 5 * Hq + k] = cd0;
    g_h[0][b][k] = packsplit_(hd0);
}

// ---------------------------------------------------------------------------
// K4: fused recurrence via mma.sync split-bf16 tensor cores.
//   grid = 128 = 8 batch-groups (16 b) x 16 j-slices. 256 threads.
//   Warp g (0..6) owns gate g: m16(j) x n16(b), K=320, 3-pass split-bf16.
//   A_hi in registers, A_lo in SMEM (as verified in R16).
//   Exchange: h/r packed split-bf16 in L2; per-rank flags; each staging
//   thread polls ONLY its source rank's flag (trickle staging overlaps
//   producer skew). B staging = PRMT unpack, no CVTs in the chain.
// ---------------------------------------------------------------------------
__global__ void __launch_bounds__(256, 1)
k_recur(const float* __restrict__ Wc, const float* __restrict__ ts,
        const float* __restrict__ init, const float* __restrict__ bc,
        float* __restrict__ out) {
    extern __shared__ float sh[];
    uint32_t* BH = (uint32_t*)(sh + BH_F);
    uint32_t* BL = (uint32_t*)(sh + BL_F);
    float* red = sh + RED_F;
    float* bs  = sh + BS_F;

    int tid = threadIdx.x;
    int lane = tid & 31;
    int wid = tid >> 5;
    int gp = lane >> 2, tg = lane & 3;        // mma fragment identity
    int j2 = tid & 15, b2 = tid >> 4;         // phase-2 identity
    int group = blockIdx.x >> 4;
    int rank  = blockIdx.x & 15;
    int j0 = rank * 16, jg = j0 + j2;
    int gb0 = group * 16;
    int gbb = gb0 + b2;

    int srcrank = (tid & 63) >> 2;            // rank producing this thread's h
    unsigned* srcflag = g_flag + (group * 16 + srcrank) * 8;
    unsigned* myflag  = g_flag + (group * 16 + rank) * 8;

    // ---- one-time: A_hi fragments -> registers, A_lo fragments -> SMEM ----
    uint32_t ahi[20][4];
    if (wid < 7) {
        int g = wid;
        #pragma unroll
        for (int kk = 0; kk < 20; kk++) {
            #pragma unroll
            for (int fi = 0; fi < 4; fi++) {
                int r = gp + (fi & 1) * 8;                 // j row 0..15
                int c = kk * 16 + tg * 2 + (fi >> 1) * 8;  // k col
                int col0 = (c < 256) ? (Eq + c) : (c - 256);
                int col1 = (c + 1 < 256) ? (Eq + c + 1) : (c + 1 - 256);
                size_t rowoff = (size_t)(g * Hq + j0 + r) * KIN;
                float w0 = Wc[rowoff + col0];
                float w1 = Wc[rowoff + col1];
                unsigned h0, l0, h1, l1;
                bf16split_(w0, h0, l0);
                bf16split_(w1, h1, l1);
                ahi[kk][fi] = h0 | (h1 << 16);
                ((uint32_t*)sh)[ALO_F + ((wid * 20 + kk) * 32 + lane) * 4 + fi] =
                    l0 | (l1 << 16);
            }
        }
    }
    if (tid < 112) bs[tid] = bc[(tid >> 4) * Hq + j0 + (tid & 15)];

    float c_st  = tanhf(init[3 * Hq + jg]);
    float cb_st = tanhf(init[2 * Hq + jg]);
    __syncthreads();

    const uint4* gr4 = (const uint4*)g_r;

    // prefetch regs (t = 0; h(0) from k_init, launch-ordered)
    uint4 ph[4], pr;
    float ptc, ptp = 0.f;
    {
        const uint4* gsrc = (const uint4*)&g_h[0][0][0];
        #pragma unroll
        for (int i = 0; i < 4; i++) {
            int idx = tid + 256 * i;
            ph[i] = __ldcg(gsrc + (gb0 + (idx >> 6)) * 64 + (idx & 63));
        }
        pr  = gr4[((size_t)gbb * Tq + 0) * 16 + j2];
        ptc = ts[gbb * Tq + 0];
    }

    for (int t = 0; t < Tq; t++) {
        // ---- stage B = [h | r] via PRMT (lo16 = hi-bf16, hi16 = lo-bf16) ----
        #pragma unroll
        for (int i = 0; i < 4; i++) {
            int idx = tid + 256 * i;
            int b = idx >> 6, kq = idx & 63;
            unsigned bh0 = prmt_(ph[i].x, ph[i].y, 0x5410);
            unsigned bh1 = prmt_(ph[i].z, ph[i].w, 0x5410);
            unsigned bl0 = prmt_(ph[i].x, ph[i].y, 0x7632);
            unsigned bl1 = prmt_(ph[i].z, ph[i].w, 0x7632);
            *(ull*)&BH[b * 164 + 2 * kq] = (ull)bh0 | ((ull)bh1 << 32);
            *(ull*)&BL[b * 164 + 2 * kq] = (ull)bl0 | ((ull)bl1 << 32);
        }
        {
            unsigned bh0 = prmt_(pr.x, pr.y, 0x5410);
            unsigned bh1 = prmt_(pr.z, pr.w, 0x5410);
            unsigned bl0 = prmt_(pr.x, pr.y, 0x7632);
            unsigned bl1 = prmt_(pr.z, pr.w, 0x7632);
            *(ull*)&BH[b2 * 164 + 128 + 2 * j2] = (ull)bh0 | ((ull)bh1 << 32);
            *(ull*)&BL[b2 * 164 + 128 + 2 * j2] = (ull)bl0 | ((ull)bl1 << 32);
        }
        float tc = ptc, tp = ptp;
        __syncthreads();

        // ---- GEMM: warps 0..6, 3-pass split-bf16 mma ----
        if (wid < 7) {
            float d[2][4];
            #pragma unroll
            for (int nt = 0; nt < 2; nt++)
                #pragma unroll
                for (int i = 0; i < 4; i++) d[nt][i] = 0.f;

            #pragma unroll
            for (int kk = 0; kk < 20; kk++) {
                float4 al4 = *(const float4*)&sh[ALO_F
                               + ((wid * 20 + kk) * 32 + lane) * 4];
                uint32_t al[4] = {__float_as_uint(al4.x), __float_as_uint(al4.y),
                                  __float_as_uint(al4.z), __float_as_uint(al4.w)};
                #pragma unroll
                for (int nt = 0; nt < 2; nt++) {
                    int nb = nt * 8 + gp;
                    uint32_t bh0 = BH[nb * 164 + kk * 8 + tg];
                    uint32_t bh1 = BH[nb * 164 + kk * 8 + tg + 4];
                    uint32_t bl0 = BL[nb * 164 + kk * 8 + tg];
                    uint32_t bl1 = BL[nb * 164 + kk * 8 + tg + 4];
                    MMA_(d[nt], ahi[kk], bh0, bh1);
                    MMA_(d[nt], ahi[kk], bl0, bl1);
                    MMA_(d[nt], al, bh0, bh1);
                }
            }

            // epilogue: D frags -> red[(g*16+j)*18 + b]
            #pragma unroll
            for (int nt = 0; nt < 2; nt++) {
                int b = nt * 8 + tg * 2;
                *(float2*)&red[(wid * 16 + gp) * 18 + b] =
                    make_float2(d[nt][0], d[nt][1]);
                *(float2*)&red[(wid * 16 + gp + 8) * 18 + b] =
                    make_float2(d[nt][2], d[nt][3]);
            }
        }
        __syncthreads();

        // ---- phase 2: gates + decay + state update (1 out/thread) ----
        float gate[7];
        #pragma unroll
        for (int g = 0; g < 7; g++)
            gate[g] = red[(g * 16 + j2) * 18 + b2] + bs[g * 16 + j2];

        float gi  = sigf(gate[0]);
        float gf  = sigf(gate[1]);
        float gz  = tanf_(gate[2]);
        float go  = sigf(gate[3]);
        float gib = sigf(gate[4]);
        float gfb = sigf(gate[5]);
        float gd  = splusf(gate[6]);
        float dt  = tc - tp;

        float ct  = gf * c_st + gi * gz;
        float cbt = gfb * cb_st + gib * gz;
        float cdt = cbt + (ct - cbt) * __expf(-gd * dt);
        float hdt = go * tanf_(cdt);

        c_st = ct; cb_st = cbt;
        __stcg(&g_h[(t & 1) ^ 1][gbb][jg], packsplit_(hdt));

        // ---- release: bar orders all 256 stcg, tid0 publishes own flag ----
        __syncthreads();
        if (tid == 0)
            asm volatile("st.release.gpu.global.u32 [%0], %1;"
                         :: "l"(myflag), "r"((unsigned)(t + 1)) : "memory");

        // ---- out writes AFTER release ----
        size_t ob = ((size_t)gbb * (Tq + 1) + t + 1) * (size_t)(6 * Hq) + jg;
        __stcs(&out[ob + 0 * Hq], hdt);
        __stcs(&out[ob + 1 * Hq], go);
        __stcs(&out[ob + 2 * Hq], cbt);
        __stcs(&out[ob + 3 * Hq], ct);
        __stcs(&out[ob + 4 * Hq], gd);
        __stcs(&out[ob + 5 * Hq], cdt);

        // ---- poll own SOURCE rank's flag, then prefetch (trickle) ----
        if (t < Tq - 1) {
            unsigned tgt = (unsigned)(t + 1);
            bool ok;
            do {
                unsigned f;
                asm volatile("ld.acquire.gpu.global.u32 %0, [%1];"
                             : "=r"(f) : "l"(srcflag) : "memory");
                ok = __all_sync(0xffffffffu, f >= tgt);
            } while (!ok);

            const uint4* gsrc = (const uint4*)&g_h[(t + 1) & 1][0][0];
            #pragma unroll
            for (int i = 0; i < 4; i++) {
                int idx = tid + 256 * i;
                ph[i] = __ldcg(gsrc + (gb0 + (idx >> 6)) * 64 + (idx & 63));
            }
            pr  = gr4[((size_t)gbb * Tq + t + 1) * 16 + j2];
            ptp = tc;
            ptc = ts[gbb * Tq + t + 1];
        }
    }
}

// ---------------------------------------------------------------------------
extern "C" void kernel_launch(void* const* d_in, const int* in_sizes, int n_in,
                              void* d_out, int out_size) {
    const float* marks = (const float*)d_in[0];
    const float* ts    = (const float*)d_in[1];
    const float* Wemb  = (const float*)d_in[2];
    const float* Wc    = (const float*)d_in[3];
    const float* bc    = (const float*)d_in[4];
    const float* init  = (const float*)d_in[5];
    float* out = (float*)d_out;

    k_dummy<<<1, 32>>>();                       // aligns ncu -s 5 onto k_recur
    k_embed<<<Bq * Tq, 128>>>(marks, Wemb);
    k_init<<<Bq, 256>>>(init, out);

    const int SMEM = SMEM_FLT * (int)sizeof(float);   // 101,376 B
    cudaFuncSetAttribute(k_recur, cudaFuncAttributeMaxDynamicSharedMemorySize, SMEM);
    k_recur<<<128, 256, SMEM>>>(Wc, ts, init, bc, out);
}